// round 1
// baseline (speedup 1.0000x reference)
#include <cuda_runtime.h>
#include <math.h>

#define NN 100000
#define EE 1600000
#define DIN 100
#define DH  256
#define DPP 128
#define SCAN_B 1024
#define NBLK ((NN + SCAN_B - 1) / SCAN_B)   // 98

// ---------------- scratch (device globals; no allocation allowed) ----------
__device__ float g_agg[(size_t)NN * DH];
__device__ float g_h1 [(size_t)NN * DH];
__device__ float g_h2 [(size_t)NN * DH];
__device__ float g_z  [(size_t)NN * DPP];
__device__ int   g_deg[NN];
__device__ int   g_off[NN];
__device__ int   g_pos[NN];
__device__ float g_rdeg[NN];
__device__ int   g_csr[EE];
__device__ int   g_bsum[NBLK];
__device__ float g_sum[DPP], g_sumsq[DPP], g_mu[DPP], g_rsig[DPP];

// ---------------- CSR build -------------------------------------------------
__global__ void zero_kernel() {
    int i = blockIdx.x * blockDim.x + threadIdx.x;
    if (i < NN) g_deg[i] = 0;
    if (i < DPP) { g_sum[i] = 0.f; g_sumsq[i] = 0.f; }
}

__global__ void count_deg_kernel(const int* __restrict__ ei) {
    for (int e = blockIdx.x * blockDim.x + threadIdx.x; e < EE;
         e += gridDim.x * blockDim.x) {
        atomicAdd(&g_deg[ei[EE + e]], 1);
    }
}

__global__ void scan1_kernel() {
    __shared__ int sh[SCAN_B];
    int tid = threadIdx.x;
    int i = blockIdx.x * SCAN_B + tid;
    int v = (i < NN) ? g_deg[i] : 0;
    sh[tid] = v;
    __syncthreads();
    for (int off = 1; off < SCAN_B; off <<= 1) {
        int t = (tid >= off) ? sh[tid - off] : 0;
        __syncthreads();
        sh[tid] += t;
        __syncthreads();
    }
    if (i < NN) g_off[i] = sh[tid] - v;   // exclusive
    if (tid == SCAN_B - 1) g_bsum[blockIdx.x] = sh[tid];
}

__global__ void scan2_kernel() {
    if (threadIdx.x == 0 && blockIdx.x == 0) {
        int acc = 0;
        for (int b = 0; b < NBLK; b++) { int t = g_bsum[b]; g_bsum[b] = acc; acc += t; }
    }
}

__global__ void scan3_kernel() {
    int i = blockIdx.x * blockDim.x + threadIdx.x;
    if (i < NN) {
        int o = g_off[i] + g_bsum[i / SCAN_B];
        g_off[i] = o;
        g_pos[i] = o;
        int d = g_deg[i];
        g_rdeg[i] = 1.f / (float)(d > 1 ? d : 1);
    }
}

__global__ void fill_csr_kernel(const int* __restrict__ ei) {
    for (int e = blockIdx.x * blockDim.x + threadIdx.x; e < EE;
         e += gridDim.x * blockDim.x) {
        int dst = ei[EE + e];
        int p = atomicAdd(&g_pos[dst], 1);
        g_csr[p] = ei[e];
    }
}

// ---------------- aggregation (mean of neighbor features) -------------------
// one warp per node, d == 256, float4 x2 per lane
__global__ void agg256_kernel(const float* __restrict__ xin, float* __restrict__ out) {
    int gw = (blockIdx.x * blockDim.x + threadIdx.x) >> 5;
    int lane = threadIdx.x & 31;
    if (gw >= NN) return;
    int beg = g_off[gw];
    int cnt = g_deg[gw];
    float4 a0 = make_float4(0.f, 0.f, 0.f, 0.f);
    float4 a1 = make_float4(0.f, 0.f, 0.f, 0.f);
    for (int j = 0; j < cnt; j++) {
        int s = g_csr[beg + j];
        const float4* row = (const float4*)(xin + (size_t)s * DH);
        float4 v0 = row[lane];
        float4 v1 = row[lane + 32];
        a0.x += v0.x; a0.y += v0.y; a0.z += v0.z; a0.w += v0.w;
        a1.x += v1.x; a1.y += v1.y; a1.z += v1.z; a1.w += v1.w;
    }
    float rd = g_rdeg[gw];
    a0.x *= rd; a0.y *= rd; a0.z *= rd; a0.w *= rd;
    a1.x *= rd; a1.y *= rd; a1.z *= rd; a1.w *= rd;
    float4* o = (float4*)(out + (size_t)gw * DH);
    o[lane] = a0;
    o[lane + 32] = a1;
}

// generic d (used for d = 100), scalar path
__global__ void agg_gen_kernel(const float* __restrict__ xin, int d,
                               float* __restrict__ out) {
    int gw = (blockIdx.x * blockDim.x + threadIdx.x) >> 5;
    int lane = threadIdx.x & 31;
    if (gw >= NN) return;
    int beg = g_off[gw];
    int cnt = g_deg[gw];
    float acc[4] = {0.f, 0.f, 0.f, 0.f};
    for (int j = 0; j < cnt; j++) {
        int s = g_csr[beg + j];
        const float* row = xin + (size_t)s * d;
#pragma unroll
        for (int t = 0; t < 4; t++) {
            int c = lane + 32 * t;
            if (c < d) acc[t] += row[c];
        }
    }
    float rd = g_rdeg[gw];
#pragma unroll
    for (int t = 0; t < 4; t++) {
        int c = lane + 32 * t;
        if (c < d) out[(size_t)gw * d + c] = acc[t] * rd;
    }
}

// ---------------- dual-operand SGEMM ----------------------------------------
// Y[m,n] = sum_k A[m,k]*Wl[n,k] (+ sum_k X[m,k]*Wr[n,k]) + bias[n], opt ReLU
// 128x128 block tile, 8x8 per thread, BK=8, 256 threads
template <bool DUAL, bool RELU>
__global__ void __launch_bounds__(256)
gemm_kernel(const float* __restrict__ A, const float* __restrict__ X,
            const float* __restrict__ Wl, const float* __restrict__ Wr,
            const float* __restrict__ bias, float* __restrict__ Y,
            int M, int Nn, int K) {
    __shared__ float sA[8][132];
    __shared__ float sX[8][132];
    __shared__ float sWl[8][132];
    __shared__ float sWr[8][132];

    int tid = threadIdx.x;
    int tx = tid & 15;
    int ty = tid >> 4;
    int m0 = blockIdx.y * 128;
    int n0 = blockIdx.x * 128;

    float acc[8][8];
#pragma unroll
    for (int i = 0; i < 8; i++)
#pragma unroll
        for (int j = 0; j < 8; j++) acc[i][j] = 0.f;

    int row = tid >> 1;           // 0..127
    int kp  = (tid & 1) * 4;      // 0 or 4

    for (int k0 = 0; k0 < K; k0 += 8) {
        int m = m0 + row;
        int n = n0 + row;
#pragma unroll
        for (int i = 0; i < 4; i++) {
            int k = k0 + kp + i;
            float av = 0.f, xv = 0.f, wv = 0.f, wrv = 0.f;
            if (k < K) {
                if (m < M) {
                    av = A[(size_t)m * K + k];
                    if (DUAL) xv = X[(size_t)m * K + k];
                }
                wv = Wl[(size_t)n * K + k];
                if (DUAL) wrv = Wr[(size_t)n * K + k];
            }
            sA[kp + i][row] = av;
            sWl[kp + i][row] = wv;
            if (DUAL) {
                sX[kp + i][row] = xv;
                sWr[kp + i][row] = wrv;
            }
        }
        __syncthreads();
#pragma unroll
        for (int kk = 0; kk < 8; kk++) {
            float4 a0 = *(const float4*)&sA[kk][ty * 8];
            float4 a1 = *(const float4*)&sA[kk][ty * 8 + 4];
            float4 w0 = *(const float4*)&sWl[kk][tx * 8];
            float4 w1 = *(const float4*)&sWl[kk][tx * 8 + 4];
            float af[8] = {a0.x, a0.y, a0.z, a0.w, a1.x, a1.y, a1.z, a1.w};
            float wf[8] = {w0.x, w0.y, w0.z, w0.w, w1.x, w1.y, w1.z, w1.w};
#pragma unroll
            for (int i = 0; i < 8; i++)
#pragma unroll
                for (int j = 0; j < 8; j++) acc[i][j] += af[i] * wf[j];
            if (DUAL) {
                float4 x0 = *(const float4*)&sX[kk][ty * 8];
                float4 x1 = *(const float4*)&sX[kk][ty * 8 + 4];
                float4 r0 = *(const float4*)&sWr[kk][tx * 8];
                float4 r1 = *(const float4*)&sWr[kk][tx * 8 + 4];
                float xf[8] = {x0.x, x0.y, x0.z, x0.w, x1.x, x1.y, x1.z, x1.w};
                float rf[8] = {r0.x, r0.y, r0.z, r0.w, r1.x, r1.y, r1.z, r1.w};
#pragma unroll
                for (int i = 0; i < 8; i++)
#pragma unroll
                    for (int j = 0; j < 8; j++) acc[i][j] += xf[i] * rf[j];
            }
        }
        __syncthreads();
    }

#pragma unroll
    for (int i = 0; i < 8; i++) {
        int m = m0 + ty * 8 + i;
        if (m >= M) continue;
#pragma unroll
        for (int j = 0; j < 8; j++) {
            int n = n0 + tx * 8 + j;
            float v = acc[i][j] + bias[n];
            if (RELU) v = fmaxf(v, 0.f);
            Y[(size_t)m * Nn + n] = v;
        }
    }
}

// ---------------- BatchNorm --------------------------------------------------
__global__ void bn_reduce_kernel() {
    int c = threadIdx.x;   // 0..127
    float s = 0.f, s2 = 0.f;
    for (int m = blockIdx.x; m < NN; m += gridDim.x) {
        float v = g_z[(size_t)m * DPP + c];
        s += v;
        s2 += v * v;
    }
    atomicAdd(&g_sum[c], s);
    atomicAdd(&g_sumsq[c], s2);
}

__global__ void bn_fin_kernel() {
    int c = threadIdx.x;
    if (c < DPP) {
        float mu = g_sum[c] / (float)NN;
        float var = g_sumsq[c] / (float)NN - mu * mu;
        g_mu[c] = mu;
        g_rsig[c] = rsqrtf(var + 1e-5f);
    }
}

__global__ void bn_apply_kernel(const float* __restrict__ gamma,
                                const float* __restrict__ beta,
                                float* __restrict__ h) {
    for (size_t idx = (size_t)blockIdx.x * blockDim.x + threadIdx.x;
         idx < (size_t)NN * DPP; idx += (size_t)gridDim.x * blockDim.x) {
        int c = (int)(idx & (DPP - 1));
        float v = g_z[idx];
        h[idx] = gamma[c] * (v - g_mu[c]) * g_rsig[c] + beta[c];
    }
}

// ---------------- launch -----------------------------------------------------
extern "C" void kernel_launch(void* const* d_in, const int* in_sizes, int n_in,
                              void* d_out, int out_size) {
    const float* x    = (const float*)d_in[0];
    const int*   ei   = (const int*)d_in[1];
    const float* Wl0  = (const float*)d_in[2];
    const float* bl0  = (const float*)d_in[3];
    const float* Wr0  = (const float*)d_in[4];
    const float* Wl1  = (const float*)d_in[5];
    const float* bl1  = (const float*)d_in[6];
    const float* Wr1  = (const float*)d_in[7];
    const float* Wl2  = (const float*)d_in[8];
    const float* bl2  = (const float*)d_in[9];
    const float* Wr2  = (const float*)d_in[10];
    const float* Wp   = (const float*)d_in[11];
    const float* bp   = (const float*)d_in[12];
    const float* gamma = (const float*)d_in[13];
    const float* beta  = (const float*)d_in[14];

    float* out = (float*)d_out;
    float* x3 = out;                          // [N, 256]
    float* h  = out + (size_t)NN * DH;        // [N, 128]

    float *agg, *h1, *h2, *z;
    cudaGetSymbolAddress((void**)&agg, g_agg);
    cudaGetSymbolAddress((void**)&h1, g_h1);
    cudaGetSymbolAddress((void**)&h2, g_h2);
    cudaGetSymbolAddress((void**)&z, g_z);

    // CSR build
    zero_kernel<<<(NN + 255) / 256, 256>>>();
    count_deg_kernel<<<2048, 256>>>(ei);
    scan1_kernel<<<NBLK, SCAN_B>>>();
    scan2_kernel<<<1, 32>>>();
    scan3_kernel<<<(NN + 255) / 256, 256>>>();
    fill_csr_kernel<<<2048, 256>>>(ei);

    dim3 gthr(256);
    int aggBlocks = (NN + 7) / 8;   // 8 warps per block, 1 warp/node

    // layer 0: d = 100
    agg_gen_kernel<<<aggBlocks, 256>>>(x, DIN, agg);
    {
        dim3 grid(DH / 128, (NN + 127) / 128);
        gemm_kernel<true, true><<<grid, 256>>>(agg, x, Wl0, Wr0, bl0, h1, NN, DH, DIN);
    }
    // layer 1: d = 256
    agg256_kernel<<<aggBlocks, 256>>>(h1, agg);
    {
        dim3 grid(DH / 128, (NN + 127) / 128);
        gemm_kernel<true, true><<<grid, 256>>>(agg, h1, Wl1, Wr1, bl1, h2, NN, DH, DH);
    }
    // layer 2: d = 256, no relu, writes x3 directly into d_out
    agg256_kernel<<<aggBlocks, 256>>>(h2, agg);
    {
        dim3 grid(DH / 128, (NN + 127) / 128);
        gemm_kernel<true, false><<<grid, 256>>>(agg, h2, Wl2, Wr2, bl2, x3, NN, DH, DH);
    }
    // projection: z = x3 @ Wp^T + bp
    {
        dim3 grid(DPP / 128, (NN + 127) / 128);
        gemm_kernel<false, false><<<grid, 256>>>(x3, x3, Wp, Wp, bp, z, NN, DPP, DH);
    }
    // BatchNorm
    bn_reduce_kernel<<<512, DPP>>>();
    bn_fin_kernel<<<1, DPP>>>();
    bn_apply_kernel<<<2048, 256>>>(gamma, beta, h);
}

// round 3
// speedup vs baseline: 1.7790x; 1.7790x over previous
#include <cuda_runtime.h>
#include <cuda_bf16.h>
#include <math.h>

#define NN 100000
#define EE 1600000
#define DIN 100
#define DH  256
#define DPP 128
#define SCAN_B 1024
#define NBLK ((NN + SCAN_B - 1) / SCAN_B)   // 98

// ---------------- scratch (device globals; no allocation allowed) ----------
__device__ float g_agg[(size_t)NN * DH];
__device__ float g_h1 [(size_t)NN * DH];
__device__ float g_h2 [(size_t)NN * DH];
__device__ float g_z  [(size_t)NN * DPP];
__device__ int   g_deg[NN];
__device__ int   g_off[NN];
__device__ int   g_pos[NN];
__device__ float g_rdeg[NN];
__device__ int   g_csr[EE];
__device__ int   g_bsum[NBLK];
__device__ float g_sum[DPP], g_sumsq[DPP], g_mu[DPP], g_rsig[DPP];

// ---------------- CSR build -------------------------------------------------
__global__ void zero_kernel() {
    int i = blockIdx.x * blockDim.x + threadIdx.x;
    if (i < NN) g_deg[i] = 0;
    if (i < DPP) { g_sum[i] = 0.f; g_sumsq[i] = 0.f; }
}

__global__ void count_deg_kernel(const int* __restrict__ ei) {
    for (int e = blockIdx.x * blockDim.x + threadIdx.x; e < EE;
         e += gridDim.x * blockDim.x) {
        atomicAdd(&g_deg[ei[EE + e]], 1);
    }
}

__global__ void scan1_kernel() {
    __shared__ int sh[SCAN_B];
    int tid = threadIdx.x;
    int i = blockIdx.x * SCAN_B + tid;
    int v = (i < NN) ? g_deg[i] : 0;
    sh[tid] = v;
    __syncthreads();
    for (int off = 1; off < SCAN_B; off <<= 1) {
        int t = (tid >= off) ? sh[tid - off] : 0;
        __syncthreads();
        sh[tid] += t;
        __syncthreads();
    }
    if (i < NN) g_off[i] = sh[tid] - v;   // exclusive
    if (tid == SCAN_B - 1) g_bsum[blockIdx.x] = sh[tid];
}

__global__ void scan2_kernel() {
    if (threadIdx.x == 0 && blockIdx.x == 0) {
        int acc = 0;
        for (int b = 0; b < NBLK; b++) { int t = g_bsum[b]; g_bsum[b] = acc; acc += t; }
    }
}

__global__ void scan3_kernel() {
    int i = blockIdx.x * blockDim.x + threadIdx.x;
    if (i < NN) {
        int o = g_off[i] + g_bsum[i / SCAN_B];
        g_off[i] = o;
        g_pos[i] = o;
        int d = g_deg[i];
        g_rdeg[i] = 1.f / (float)(d > 1 ? d : 1);
    }
}

__global__ void fill_csr_kernel(const int* __restrict__ ei) {
    for (int e = blockIdx.x * blockDim.x + threadIdx.x; e < EE;
         e += gridDim.x * blockDim.x) {
        int dst = ei[EE + e];
        int p = atomicAdd(&g_pos[dst], 1);
        g_csr[p] = ei[e];
    }
}

// ---------------- aggregation (mean of neighbor features) -------------------
__global__ void agg256_kernel(const float* __restrict__ xin, float* __restrict__ out) {
    int gw = (blockIdx.x * blockDim.x + threadIdx.x) >> 5;
    int lane = threadIdx.x & 31;
    if (gw >= NN) return;
    int beg = g_off[gw];
    int cnt = g_deg[gw];
    float4 a0 = make_float4(0.f, 0.f, 0.f, 0.f);
    float4 a1 = make_float4(0.f, 0.f, 0.f, 0.f);
    for (int j = 0; j < cnt; j++) {
        int s = g_csr[beg + j];
        const float4* row = (const float4*)(xin + (size_t)s * DH);
        float4 v0 = row[lane];
        float4 v1 = row[lane + 32];
        a0.x += v0.x; a0.y += v0.y; a0.z += v0.z; a0.w += v0.w;
        a1.x += v1.x; a1.y += v1.y; a1.z += v1.z; a1.w += v1.w;
    }
    float rd = g_rdeg[gw];
    a0.x *= rd; a0.y *= rd; a0.z *= rd; a0.w *= rd;
    a1.x *= rd; a1.y *= rd; a1.z *= rd; a1.w *= rd;
    float4* o = (float4*)(out + (size_t)gw * DH);
    o[lane] = a0;
    o[lane + 32] = a1;
}

__global__ void agg_gen_kernel(const float* __restrict__ xin, int d,
                               float* __restrict__ out) {
    int gw = (blockIdx.x * blockDim.x + threadIdx.x) >> 5;
    int lane = threadIdx.x & 31;
    if (gw >= NN) return;
    int beg = g_off[gw];
    int cnt = g_deg[gw];
    float acc[4] = {0.f, 0.f, 0.f, 0.f};
    for (int j = 0; j < cnt; j++) {
        int s = g_csr[beg + j];
        const float* row = xin + (size_t)s * d;
#pragma unroll
        for (int t = 0; t < 4; t++) {
            int c = lane + 32 * t;
            if (c < d) acc[t] += row[c];
        }
    }
    float rd = g_rdeg[gw];
#pragma unroll
    for (int t = 0; t < 4; t++) {
        int c = lane + 32 * t;
        if (c < d) out[(size_t)gw * d + c] = acc[t] * rd;
    }
}

// ---------------- bf16x2-split tensor-core GEMM -----------------------------
// Y[m,n] = sum_k A[m,k]*Wl[n,k] (+ sum_k X[m,k]*Wr[n,k]) + bias[n], opt ReLU.
// fp32 emulated as (hi + lo) bf16; 3 MMAs per product term, fp32 accumulate.
// CTA tile 128x128, BK=16, 256 threads = 8 warps (2M x 4N), warp tile 64x32.

#define SROW 9   // u32 row stride (8 k-pairs + 1 pad)

__device__ __forceinline__ void split2(float v0, float v1,
                                       unsigned& hi, unsigned& lo) {
    float h0 = __bfloat162float(__float2bfloat16(v0));
    float h1 = __bfloat162float(__float2bfloat16(v1));
    float l0 = v0 - h0;
    float l1 = v1 - h1;
    asm("cvt.rn.bf16x2.f32 %0, %1, %2;" : "=r"(hi) : "f"(h1), "f"(h0));
    asm("cvt.rn.bf16x2.f32 %0, %1, %2;" : "=r"(lo) : "f"(l1), "f"(l0));
}

__device__ __forceinline__ void mma16816(float c[4], const unsigned a[4],
                                         const unsigned b[2]) {
    asm volatile(
        "mma.sync.aligned.m16n8k16.row.col.f32.bf16.bf16.f32 "
        "{%0,%1,%2,%3}, {%4,%5,%6,%7}, {%8,%9}, {%0,%1,%2,%3};"
        : "+f"(c[0]), "+f"(c[1]), "+f"(c[2]), "+f"(c[3])
        : "r"(a[0]), "r"(a[1]), "r"(a[2]), "r"(a[3]), "r"(b[0]), "r"(b[1]));
}

template <bool DUAL, bool RELU>
__global__ void __launch_bounds__(256, 1)
mma_gemm_kernel(const float* __restrict__ A0, const float* __restrict__ X0,
                const float* __restrict__ Wl0, const float* __restrict__ Wr0,
                const float* __restrict__ bias, float* __restrict__ Y,
                int M, int Nn, int K) {
    // smem: [buf][tile: 0=Ahi 1=Alo 2=Whi 3=Wlo][128*SROW u32]
    __shared__ unsigned sm[2][4][128 * SROW];

    const int tid = threadIdx.x;
    const int lane = tid & 31;
    const int wid = tid >> 5;
    const int wm = wid & 1;        // warp row (M)
    const int wn = wid >> 1;       // warp col (N)
    const int g = lane >> 2;       // group id 0..7
    const int tq = lane & 3;       // thread in group

    const int m0 = blockIdx.y * 128;
    const int n0 = blockIdx.x * 128;

    const int ldr = tid >> 2;      // loader row 0..63
    const int ldq = tid & 3;       // loader quad 0..3

    const int s0 = (K + 15) / 16;
    const int nsteps = DUAL ? 2 * s0 : s0;

    float acc[4][4][4];
#pragma unroll
    for (int i = 0; i < 4; i++)
#pragma unroll
        for (int j = 0; j < 4; j++)
#pragma unroll
            for (int e = 0; e < 4; e++) acc[i][j][e] = 0.f;

    float4 stA[2], stW[2];

    // ---- global load into registers for a step ----
    auto gload = [&](int s) {
        const float* Ap;
        const float* Wp;
        int k0;
        if (!DUAL || s < s0) { Ap = A0; Wp = Wl0; k0 = s * 16; }
        else                 { Ap = X0; Wp = Wr0; k0 = (s - s0) * 16; }
        int k = k0 + ldq * 4;
#pragma unroll
        for (int h = 0; h < 2; h++) {
            int row = ldr + 64 * h;
            float4 v = make_float4(0.f, 0.f, 0.f, 0.f);
            int gm = m0 + row;
            if (gm < M) {
                const float* p = Ap + (size_t)gm * K;
                if (k + 3 < K) v = *(const float4*)(p + k);
                else {
                    if (k < K)     v.x = p[k];
                    if (k + 1 < K) v.y = p[k + 1];
                    if (k + 2 < K) v.z = p[k + 2];
                }
            }
            stA[h] = v;
            float4 u = make_float4(0.f, 0.f, 0.f, 0.f);
            int gn = n0 + row;
            if (gn < Nn) {
                const float* pw = Wp + (size_t)gn * K;
                if (k + 3 < K) u = *(const float4*)(pw + k);
                else {
                    if (k < K)     u.x = pw[k];
                    if (k + 1 < K) u.y = pw[k + 1];
                    if (k + 2 < K) u.z = pw[k + 2];
                }
            }
            stW[h] = u;
        }
    };

    // ---- convert + store staged registers to smem buffer ----
    auto sstore = [&](int buf) {
        unsigned* sAh = sm[buf][0];
        unsigned* sAl = sm[buf][1];
        unsigned* sWh = sm[buf][2];
        unsigned* sWl = sm[buf][3];
#pragma unroll
        for (int h = 0; h < 2; h++) {
            int row = ldr + 64 * h;
            unsigned hp0, lp0, hp1, lp1;
            split2(stA[h].x, stA[h].y, hp0, lp0);
            split2(stA[h].z, stA[h].w, hp1, lp1);
            sAh[row * SROW + 2 * ldq]     = hp0;
            sAh[row * SROW + 2 * ldq + 1] = hp1;
            sAl[row * SROW + 2 * ldq]     = lp0;
            sAl[row * SROW + 2 * ldq + 1] = lp1;
            split2(stW[h].x, stW[h].y, hp0, lp0);
            split2(stW[h].z, stW[h].w, hp1, lp1);
            sWh[row * SROW + 2 * ldq]     = hp0;
            sWh[row * SROW + 2 * ldq + 1] = hp1;
            sWl[row * SROW + 2 * ldq]     = lp0;
            sWl[row * SROW + 2 * ldq + 1] = lp1;
        }
    };

    // ---- compute one k-step from smem buffer ----
    auto compute = [&](int buf) {
        const unsigned* sAh = sm[buf][0];
        const unsigned* sAl = sm[buf][1];
        const unsigned* sWh = sm[buf][2];
        const unsigned* sWl = sm[buf][3];
        unsigned bh[4][2], bl[4][2];
#pragma unroll
        for (int nb = 0; nb < 4; nb++) {
            int n = wn * 32 + nb * 8 + g;
            bh[nb][0] = sWh[n * SROW + tq];
            bh[nb][1] = sWh[n * SROW + tq + 4];
            bl[nb][0] = sWl[n * SROW + tq];
            bl[nb][1] = sWl[n * SROW + tq + 4];
        }
#pragma unroll
        for (int mr = 0; mr < 4; mr++) {
            int r0 = wm * 64 + mr * 16 + g;
            unsigned ah[4], al[4];
            ah[0] = sAh[r0 * SROW + tq];
            ah[1] = sAh[(r0 + 8) * SROW + tq];
            ah[2] = sAh[r0 * SROW + tq + 4];
            ah[3] = sAh[(r0 + 8) * SROW + tq + 4];
            al[0] = sAl[r0 * SROW + tq];
            al[1] = sAl[(r0 + 8) * SROW + tq];
            al[2] = sAl[r0 * SROW + tq + 4];
            al[3] = sAl[(r0 + 8) * SROW + tq + 4];
#pragma unroll
            for (int nb = 0; nb < 4; nb++) {
                mma16816(acc[mr][nb], ah, bh[nb]);
                mma16816(acc[mr][nb], ah, bl[nb]);
                mma16816(acc[mr][nb], al, bh[nb]);
            }
        }
    };

    // ---- pipeline ----
    gload(0);
    sstore(0);
    __syncthreads();
    for (int s = 0; s < nsteps; s++) {
        if (s + 1 < nsteps) gload(s + 1);
        compute(s & 1);
        if (s + 1 < nsteps) sstore((s + 1) & 1);
        __syncthreads();
    }

    // ---- epilogue ----
#pragma unroll
    for (int mr = 0; mr < 4; mr++) {
#pragma unroll
        for (int nb = 0; nb < 4; nb++) {
            int n = n0 + wn * 32 + nb * 8 + tq * 2;
            float b0 = bias[n];
            float b1 = bias[n + 1];
            int mA = m0 + wm * 64 + mr * 16 + g;
            int mB = mA + 8;
            float v0 = acc[mr][nb][0] + b0;
            float v1 = acc[mr][nb][1] + b1;
            float v2 = acc[mr][nb][2] + b0;
            float v3 = acc[mr][nb][3] + b1;
            if (RELU) {
                v0 = fmaxf(v0, 0.f); v1 = fmaxf(v1, 0.f);
                v2 = fmaxf(v2, 0.f); v3 = fmaxf(v3, 0.f);
            }
            if (mA < M) *(float2*)(Y + (size_t)mA * Nn + n) = make_float2(v0, v1);
            if (mB < M) *(float2*)(Y + (size_t)mB * Nn + n) = make_float2(v2, v3);
        }
    }
}

// ---------------- BatchNorm --------------------------------------------------
__global__ void bn_reduce_kernel() {
    int c = threadIdx.x;   // 0..127
    float s = 0.f, s2 = 0.f;
    for (int m = blockIdx.x; m < NN; m += gridDim.x) {
        float v = g_z[(size_t)m * DPP + c];
        s += v;
        s2 += v * v;
    }
    atomicAdd(&g_sum[c], s);
    atomicAdd(&g_sumsq[c], s2);
}

__global__ void bn_fin_kernel() {
    int c = threadIdx.x;
    if (c < DPP) {
        float mu = g_sum[c] / (float)NN;
        float var = g_sumsq[c] / (float)NN - mu * mu;
        g_mu[c] = mu;
        g_rsig[c] = rsqrtf(var + 1e-5f);
    }
}

__global__ void bn_apply_kernel(const float* __restrict__ gamma,
                                const float* __restrict__ beta,
                                float* __restrict__ h) {
    for (size_t idx = (size_t)blockIdx.x * blockDim.x + threadIdx.x;
         idx < (size_t)NN * DPP; idx += (size_t)gridDim.x * blockDim.x) {
        int c = (int)(idx & (DPP - 1));
        float v = g_z[idx];
        h[idx] = gamma[c] * (v - g_mu[c]) * g_rsig[c] + beta[c];
    }
}

// ---------------- launch -----------------------------------------------------
extern "C" void kernel_launch(void* const* d_in, const int* in_sizes, int n_in,
                              void* d_out, int out_size) {
    const float* x    = (const float*)d_in[0];
    const int*   ei   = (const int*)d_in[1];
    const float* Wl0  = (const float*)d_in[2];
    const float* bl0  = (const float*)d_in[3];
    const float* Wr0  = (const float*)d_in[4];
    const float* Wl1  = (const float*)d_in[5];
    const float* bl1  = (const float*)d_in[6];
    const float* Wr1  = (const float*)d_in[7];
    const float* Wl2  = (const float*)d_in[8];
    const float* bl2  = (const float*)d_in[9];
    const float* Wr2  = (const float*)d_in[10];
    const float* Wp   = (const float*)d_in[11];
    const float* bp   = (const float*)d_in[12];
    const float* gamma = (const float*)d_in[13];
    const float* beta  = (const float*)d_in[14];

    float* out = (float*)d_out;
    float* x3 = out;                          // [N, 256]
    float* h  = out + (size_t)NN * DH;        // [N, 128]

    float *agg, *h1, *h2, *z;
    cudaGetSymbolAddress((void**)&agg, g_agg);
    cudaGetSymbolAddress((void**)&h1, g_h1);
    cudaGetSymbolAddress((void**)&h2, g_h2);
    cudaGetSymbolAddress((void**)&z, g_z);

    // CSR build
    zero_kernel<<<(NN + 255) / 256, 256>>>();
    count_deg_kernel<<<2048, 256>>>(ei);
    scan1_kernel<<<NBLK, SCAN_B>>>();
    scan2_kernel<<<1, 32>>>();
    scan3_kernel<<<(NN + 255) / 256, 256>>>();
    fill_csr_kernel<<<2048, 256>>>(ei);

    int aggBlocks = (NN + 7) / 8;   // 8 warps per block, 1 warp/node

    // layer 0: d = 100
    agg_gen_kernel<<<aggBlocks, 256>>>(x, DIN, agg);
    {
        dim3 grid(DH / 128, (NN + 127) / 128);
        mma_gemm_kernel<true, true><<<grid, 256>>>(agg, x, Wl0, Wr0, bl0, h1, NN, DH, DIN);
    }
    // layer 1: d = 256
    agg256_kernel<<<aggBlocks, 256>>>(h1, agg);
    {
        dim3 grid(DH / 128, (NN + 127) / 128);
        mma_gemm_kernel<true, true><<<grid, 256>>>(agg, h1, Wl1, Wr1, bl1, h2, NN, DH, DH);
    }
    // layer 2: d = 256, no relu, writes x3 directly into d_out
    agg256_kernel<<<aggBlocks, 256>>>(h2, agg);
    {
        dim3 grid(DH / 128, (NN + 127) / 128);
        mma_gemm_kernel<true, false><<<grid, 256>>>(agg, h2, Wl2, Wr2, bl2, x3, NN, DH, DH);
    }
    // projection: z = x3 @ Wp^T + bp
    {
        dim3 grid(DPP / 128, (NN + 127) / 128);
        mma_gemm_kernel<false, false><<<grid, 256>>>(x3, x3, Wp, Wp, bp, z, NN, DPP, DH);
    }
    // BatchNorm
    bn_reduce_kernel<<<512, DPP>>>();
    bn_fin_kernel<<<1, DPP>>>();
    bn_apply_kernel<<<2048, 256>>>(gamma, beta, h);
}

// round 4
// speedup vs baseline: 1.8379x; 1.0331x over previous
#include <cuda_runtime.h>
#include <cuda_bf16.h>
#include <math.h>

#define NN 100000
#define EE 1600000
#define DIN 100
#define KW0 56          // u32 width for K=100 padded to 112
#define DH  256
#define KW1 128         // u32 width for K=256
#define DPP 128
#define SCAN_B 1024
#define NBLK ((NN + SCAN_B - 1) / SCAN_B)   // 98

// ---------------- scratch (device globals; no allocation allowed) ----------
__device__ __align__(16) float    g_h1 [(size_t)NN * DH];
__device__ __align__(16) float    g_h2 [(size_t)NN * DH];
__device__ __align__(16) float    g_z  [(size_t)NN * DPP];
__device__ __align__(16) unsigned g_aggh[(size_t)NN * KW1];
__device__ __align__(16) unsigned g_aggl[(size_t)NN * KW1];
__device__ __align__(16) unsigned g_h1h[(size_t)NN * KW1];
__device__ __align__(16) unsigned g_h1l[(size_t)NN * KW1];
__device__ __align__(16) unsigned g_h2h[(size_t)NN * KW1];
__device__ __align__(16) unsigned g_h2l[(size_t)NN * KW1];
__device__ __align__(16) unsigned g_x3h[(size_t)NN * KW1];
__device__ __align__(16) unsigned g_x3l[(size_t)NN * KW1];
__device__ __align__(16) unsigned g_xh [(size_t)NN * KW0];
__device__ __align__(16) unsigned g_xl [(size_t)NN * KW0];
// weights split
__device__ __align__(16) unsigned g_wl0h[DH * KW0], g_wl0l[DH * KW0];
__device__ __align__(16) unsigned g_wr0h[DH * KW0], g_wr0l[DH * KW0];
__device__ __align__(16) unsigned g_wl1h[DH * KW1], g_wl1l[DH * KW1];
__device__ __align__(16) unsigned g_wr1h[DH * KW1], g_wr1l[DH * KW1];
__device__ __align__(16) unsigned g_wl2h[DH * KW1], g_wl2l[DH * KW1];
__device__ __align__(16) unsigned g_wr2h[DH * KW1], g_wr2l[DH * KW1];
__device__ __align__(16) unsigned g_wph [DPP * KW1], g_wpl[DPP * KW1];

__device__ int   g_deg[NN];
__device__ int   g_off[NN];
__device__ int   g_pos[NN];
__device__ float g_rdeg[NN];
__device__ int   g_csr[EE];
__device__ int   g_bsum[NBLK];
__device__ float g_sum[DPP], g_sumsq[DPP], g_mu[DPP], g_rsig[DPP];

// ---------------- helpers ----------------------------------------------------
__device__ __forceinline__ void split2(float v0, float v1,
                                       unsigned& hi, unsigned& lo) {
    float h0 = __bfloat162float(__float2bfloat16(v0));
    float h1 = __bfloat162float(__float2bfloat16(v1));
    float l0 = v0 - h0;
    float l1 = v1 - h1;
    asm("cvt.rn.bf16x2.f32 %0, %1, %2;" : "=r"(hi) : "f"(h1), "f"(h0));
    asm("cvt.rn.bf16x2.f32 %0, %1, %2;" : "=r"(lo) : "f"(l1), "f"(l0));
}

__device__ __forceinline__ void mma16816(float c[4], const unsigned a[4],
                                         const unsigned b[2]) {
    asm volatile(
        "mma.sync.aligned.m16n8k16.row.col.f32.bf16.bf16.f32 "
        "{%0,%1,%2,%3}, {%4,%5,%6,%7}, {%8,%9}, {%0,%1,%2,%3};"
        : "+f"(c[0]), "+f"(c[1]), "+f"(c[2]), "+f"(c[3])
        : "r"(a[0]), "r"(a[1]), "r"(a[2]), "r"(a[3]), "r"(b[0]), "r"(b[1]));
}

// ---------------- CSR build -------------------------------------------------
__global__ void zero_kernel() {
    int i = blockIdx.x * blockDim.x + threadIdx.x;
    if (i < NN) g_deg[i] = 0;
    if (i < DPP) { g_sum[i] = 0.f; g_sumsq[i] = 0.f; }
}

__global__ void count_deg_kernel(const int* __restrict__ ei) {
    for (int e = blockIdx.x * blockDim.x + threadIdx.x; e < EE;
         e += gridDim.x * blockDim.x) {
        atomicAdd(&g_deg[ei[EE + e]], 1);
    }
}

__global__ void scan1_kernel() {
    __shared__ int sh[SCAN_B];
    int tid = threadIdx.x;
    int i = blockIdx.x * SCAN_B + tid;
    int v = (i < NN) ? g_deg[i] : 0;
    sh[tid] = v;
    __syncthreads();
    for (int off = 1; off < SCAN_B; off <<= 1) {
        int t = (tid >= off) ? sh[tid - off] : 0;
        __syncthreads();
        sh[tid] += t;
        __syncthreads();
    }
    if (i < NN) g_off[i] = sh[tid] - v;   // exclusive
    if (tid == SCAN_B - 1) g_bsum[blockIdx.x] = sh[tid];
}

__global__ void scan2_kernel() {
    if (threadIdx.x == 0 && blockIdx.x == 0) {
        int acc = 0;
        for (int b = 0; b < NBLK; b++) { int t = g_bsum[b]; g_bsum[b] = acc; acc += t; }
    }
}

__global__ void scan3_kernel() {
    int i = blockIdx.x * blockDim.x + threadIdx.x;
    if (i < NN) {
        int o = g_off[i] + g_bsum[i / SCAN_B];
        g_off[i] = o;
        g_pos[i] = o;
        int d = g_deg[i];
        g_rdeg[i] = 1.f / (float)(d > 1 ? d : 1);
    }
}

__global__ void fill_csr_kernel(const int* __restrict__ ei) {
    for (int e = blockIdx.x * blockDim.x + threadIdx.x; e < EE;
         e += gridDim.x * blockDim.x) {
        int dst = ei[EE + e];
        int p = atomicAdd(&g_pos[dst], 1);
        g_csr[p] = ei[e];
    }
}

// ---------------- generic fp32 -> packed bf16 hi/lo split -------------------
__global__ void split_f_kernel(const float* __restrict__ src,
                               unsigned* __restrict__ hi, unsigned* __restrict__ lo,
                               int rows, int K, int Kw) {
    size_t total = (size_t)rows * Kw;
    for (size_t idx = (size_t)blockIdx.x * blockDim.x + threadIdx.x; idx < total;
         idx += (size_t)gridDim.x * blockDim.x) {
        int r = (int)(idx / Kw);
        int c = (int)(idx % Kw);
        int k = 2 * c;
        const float* p = src + (size_t)r * K;
        float v0 = (k < K) ? p[k] : 0.f;
        float v1 = (k + 1 < K) ? p[k + 1] : 0.f;
        unsigned h, l;
        split2(v0, v1, h, l);
        hi[idx] = h;
        lo[idx] = l;
    }
}

// ---------------- aggregation (mean), emits packed hi/lo --------------------
// d = 256, one warp per node, neighbor loop unrolled x2 for MLP
__global__ void agg256s_kernel(const float* __restrict__ xin,
                               unsigned* __restrict__ oh, unsigned* __restrict__ ol) {
    int gw = (blockIdx.x * blockDim.x + threadIdx.x) >> 5;
    int lane = threadIdx.x & 31;
    if (gw >= NN) return;
    int beg = g_off[gw];
    int cnt = g_deg[gw];
    float4 a0 = make_float4(0.f, 0.f, 0.f, 0.f);
    float4 a1 = make_float4(0.f, 0.f, 0.f, 0.f);
    int j = 0;
    for (; j + 2 <= cnt; j += 2) {
        int s1 = g_csr[beg + j];
        int s2 = g_csr[beg + j + 1];
        const float4* r1 = (const float4*)(xin + (size_t)s1 * DH);
        const float4* r2 = (const float4*)(xin + (size_t)s2 * DH);
        float4 v0 = r1[lane], v1 = r1[lane + 32];
        float4 u0 = r2[lane], u1 = r2[lane + 32];
        a0.x += v0.x + u0.x; a0.y += v0.y + u0.y; a0.z += v0.z + u0.z; a0.w += v0.w + u0.w;
        a1.x += v1.x + u1.x; a1.y += v1.y + u1.y; a1.z += v1.z + u1.z; a1.w += v1.w + u1.w;
    }
    if (j < cnt) {
        int s1 = g_csr[beg + j];
        const float4* r1 = (const float4*)(xin + (size_t)s1 * DH);
        float4 v0 = r1[lane], v1 = r1[lane + 32];
        a0.x += v0.x; a0.y += v0.y; a0.z += v0.z; a0.w += v0.w;
        a1.x += v1.x; a1.y += v1.y; a1.z += v1.z; a1.w += v1.w;
    }
    float rd = g_rdeg[gw];
    a0.x *= rd; a0.y *= rd; a0.z *= rd; a0.w *= rd;
    a1.x *= rd; a1.y *= rd; a1.z *= rd; a1.w *= rd;
    unsigned h0, l0, h1, l1;
    size_t base = (size_t)gw * KW1;
    split2(a0.x, a0.y, h0, l0);
    split2(a0.z, a0.w, h1, l1);
    oh[base + lane * 2] = h0; oh[base + lane * 2 + 1] = h1;
    ol[base + lane * 2] = l0; ol[base + lane * 2 + 1] = l1;
    split2(a1.x, a1.y, h0, l0);
    split2(a1.z, a1.w, h1, l1);
    oh[base + 64 + lane * 2] = h0; oh[base + 64 + lane * 2 + 1] = h1;
    ol[base + 64 + lane * 2] = l0; ol[base + 64 + lane * 2 + 1] = l1;
}

// d = 100 (padded to Kw=56), one warp per node
__global__ void agg100s_kernel(const float* __restrict__ xin,
                               unsigned* __restrict__ oh, unsigned* __restrict__ ol) {
    int gw = (blockIdx.x * blockDim.x + threadIdx.x) >> 5;
    int lane = threadIdx.x & 31;
    if (gw >= NN) return;
    int beg = g_off[gw];
    int cnt = g_deg[gw];
    float4 a = make_float4(0.f, 0.f, 0.f, 0.f);
    bool act = lane < 25;   // 25 float4 = 100 floats
    int j = 0;
    for (; j + 2 <= cnt; j += 2) {
        int s1 = g_csr[beg + j];
        int s2 = g_csr[beg + j + 1];
        if (act) {
            const float4* r1 = (const float4*)(xin + (size_t)s1 * DIN);
            const float4* r2 = (const float4*)(xin + (size_t)s2 * DIN);
            float4 v = r1[lane];
            float4 u = r2[lane];
            a.x += v.x + u.x; a.y += v.y + u.y; a.z += v.z + u.z; a.w += v.w + u.w;
        }
    }
    if (j < cnt) {
        int s1 = g_csr[beg + j];
        if (act) {
            const float4* r1 = (const float4*)(xin + (size_t)s1 * DIN);
            float4 v = r1[lane];
            a.x += v.x; a.y += v.y; a.z += v.z; a.w += v.w;
        }
    }
    float rd = g_rdeg[gw];
    a.x *= rd; a.y *= rd; a.z *= rd; a.w *= rd;
    if (!act) { a.x = a.y = a.z = a.w = 0.f; }
    if (lane < 28) {
        unsigned h0, l0, h1, l1;
        split2(a.x, a.y, h0, l0);
        split2(a.z, a.w, h1, l1);
        size_t base = (size_t)gw * KW0;
        oh[base + lane * 2] = h0; oh[base + lane * 2 + 1] = h1;
        ol[base + lane * 2] = l0; ol[base + lane * 2 + 1] = l1;
    }
}

// ---------------- tensor-core GEMM on pre-split hi/lo operands --------------
// Y[m,n] = sum_k A[m,k]*Wl[n,k] (+ sum_k X[m,k]*Wr[n,k]) + bias[n], opt ReLU.
// CTA tile 128x128, BK=16 (8 u32), 256 threads = 8 warps (2M x 4N).

#define SROW 9   // u32 row stride (8 k-pairs + 1 pad)

template <bool DUAL, bool RELU, bool SPLIT_OUT>
__global__ void __launch_bounds__(256)
mma_gemm2_kernel(const unsigned* __restrict__ Ah, const unsigned* __restrict__ Al,
                 const unsigned* __restrict__ Xh, const unsigned* __restrict__ Xl,
                 const unsigned* __restrict__ WlH, const unsigned* __restrict__ WlL,
                 const unsigned* __restrict__ WrH, const unsigned* __restrict__ WrL,
                 const float* __restrict__ bias, float* __restrict__ Y,
                 unsigned* __restrict__ Yh, unsigned* __restrict__ Yl,
                 int M, int Nn, int KwA, int KwX) {
    __shared__ unsigned sm[2][4][128 * SROW];

    const int tid = threadIdx.x;
    const int lane = tid & 31;
    const int wid = tid >> 5;
    const int wm = wid & 1;
    const int wn = wid >> 1;
    const int g = lane >> 2;
    const int tq = lane & 3;

    const int m0 = blockIdx.y * 128;
    const int n0 = blockIdx.x * 128;

    const int row = tid >> 1;     // 0..127
    const int half = tid & 1;     // 0..1

    const int sA = KwA >> 3;
    const int nsteps = DUAL ? sA + (KwX >> 3) : sA;

    float acc[4][4][4];
#pragma unroll
    for (int i = 0; i < 4; i++)
#pragma unroll
        for (int j = 0; j < 4; j++)
#pragma unroll
            for (int e = 0; e < 4; e++) acc[i][j][e] = 0.f;

    uint4 st[4];

    auto gload = [&](int s) {
        const unsigned *Mh, *Ml, *Wh, *Wl;
        int Kw, kw0;
        if (!DUAL || s < sA) { Mh = Ah; Ml = Al; Wh = WlH; Wl = WlL; Kw = KwA; kw0 = s * 8; }
        else                 { Mh = Xh; Ml = Xl; Wh = WrH; Wl = WrL; Kw = KwX; kw0 = (s - sA) * 8; }
        int gm = m0 + row;
        int gn = n0 + row;
        size_t offm = (size_t)gm * Kw + kw0 + half * 4;
        size_t offn = (size_t)gn * Kw + kw0 + half * 4;
        uint4 z4 = make_uint4(0, 0, 0, 0);
        st[0] = (gm < M)  ? *(const uint4*)(Mh + offm) : z4;
        st[1] = (gm < M)  ? *(const uint4*)(Ml + offm) : z4;
        st[2] = (gn < Nn) ? *(const uint4*)(Wh + offn) : z4;
        st[3] = (gn < Nn) ? *(const uint4*)(Wl + offn) : z4;
    };

    auto sstore = [&](int buf) {
        int base = row * SROW + half * 4;
#pragma unroll
        for (int t = 0; t < 4; t++) {
            unsigned* p = sm[buf][t];
            p[base]     = ((const unsigned*)&st[t])[0];
            p[base + 1] = ((const unsigned*)&st[t])[1];
            p[base + 2] = ((const unsigned*)&st[t])[2];
            p[base + 3] = ((const unsigned*)&st[t])[3];
        }
    };

    auto compute = [&](int buf) {
        const unsigned* sAh = sm[buf][0];
        const unsigned* sAl = sm[buf][1];
        const unsigned* sWh = sm[buf][2];
        const unsigned* sWl = sm[buf][3];
        unsigned bh[4][2], bl[4][2];
#pragma unroll
        for (int nb = 0; nb < 4; nb++) {
            int n = wn * 32 + nb * 8 + g;
            bh[nb][0] = sWh[n * SROW + tq];
            bh[nb][1] = sWh[n * SROW + tq + 4];
            bl[nb][0] = sWl[n * SROW + tq];
            bl[nb][1] = sWl[n * SROW + tq + 4];
        }
#pragma unroll
        for (int mr = 0; mr < 4; mr++) {
            int r0 = wm * 64 + mr * 16 + g;
            unsigned ah[4], al[4];
            ah[0] = sAh[r0 * SROW + tq];
            ah[1] = sAh[(r0 + 8) * SROW + tq];
            ah[2] = sAh[r0 * SROW + tq + 4];
            ah[3] = sAh[(r0 + 8) * SROW + tq + 4];
            al[0] = sAl[r0 * SROW + tq];
            al[1] = sAl[(r0 + 8) * SROW + tq];
            al[2] = sAl[r0 * SROW + tq + 4];
            al[3] = sAl[(r0 + 8) * SROW + tq + 4];
#pragma unroll
            for (int nb = 0; nb < 4; nb++) {
                mma16816(acc[mr][nb], ah, bh[nb]);
                mma16816(acc[mr][nb], ah, bl[nb]);
                mma16816(acc[mr][nb], al, bh[nb]);
            }
        }
    };

    gload(0);
    sstore(0);
    __syncthreads();
    for (int s = 0; s < nsteps; s++) {
        if (s + 1 < nsteps) gload(s + 1);
        compute(s & 1);
        if (s + 1 < nsteps) sstore((s + 1) & 1);
        __syncthreads();
    }

    const int Nw = Nn >> 1;
#pragma unroll
    for (int mr = 0; mr < 4; mr++) {
#pragma unroll
        for (int nb = 0; nb < 4; nb++) {
            int nc = wn * 32 + nb * 8 + tq * 2;
            int n = n0 + nc;
            float b0 = bias[n];
            float b1 = bias[n + 1];
            int mA = m0 + wm * 64 + mr * 16 + g;
            int mB = mA + 8;
            float v0 = acc[mr][nb][0] + b0;
            float v1 = acc[mr][nb][1] + b1;
            float v2 = acc[mr][nb][2] + b0;
            float v3 = acc[mr][nb][3] + b1;
            if (RELU) {
                v0 = fmaxf(v0, 0.f); v1 = fmaxf(v1, 0.f);
                v2 = fmaxf(v2, 0.f); v3 = fmaxf(v3, 0.f);
            }
            if (mA < M) {
                *(float2*)(Y + (size_t)mA * Nn + n) = make_float2(v0, v1);
                if (SPLIT_OUT) {
                    unsigned hh, ll;
                    split2(v0, v1, hh, ll);
                    Yh[(size_t)mA * Nw + (n >> 1)] = hh;
                    Yl[(size_t)mA * Nw + (n >> 1)] = ll;
                }
            }
            if (mB < M) {
                *(float2*)(Y + (size_t)mB * Nn + n) = make_float2(v2, v3);
                if (SPLIT_OUT) {
                    unsigned hh, ll;
                    split2(v2, v3, hh, ll);
                    Yh[(size_t)mB * Nw + (n >> 1)] = hh;
                    Yl[(size_t)mB * Nw + (n >> 1)] = ll;
                }
            }
        }
    }
}

// ---------------- BatchNorm --------------------------------------------------
__global__ void bn_reduce_kernel() {
    int c = threadIdx.x;
    float s = 0.f, s2 = 0.f;
    for (int m = blockIdx.x; m < NN; m += gridDim.x) {
        float v = g_z[(size_t)m * DPP + c];
        s += v;
        s2 += v * v;
    }
    atomicAdd(&g_sum[c], s);
    atomicAdd(&g_sumsq[c], s2);
}

__global__ void bn_fin_kernel() {
    int c = threadIdx.x;
    if (c < DPP) {
        float mu = g_sum[c] / (float)NN;
        float var = g_sumsq[c] / (float)NN - mu * mu;
        g_mu[c] = mu;
        g_rsig[c] = rsqrtf(var + 1e-5f);
    }
}

__global__ void bn_apply_kernel(const float* __restrict__ gamma,
                                const float* __restrict__ beta,
                                float* __restrict__ h) {
    for (size_t idx = (size_t)blockIdx.x * blockDim.x + threadIdx.x;
         idx < (size_t)NN * DPP; idx += (size_t)gridDim.x * blockDim.x) {
        int c = (int)(idx & (DPP - 1));
        float v = g_z[idx];
        h[idx] = gamma[c] * (v - g_mu[c]) * g_rsig[c] + beta[c];
    }
}

// ---------------- launch -----------------------------------------------------
extern "C" void kernel_launch(void* const* d_in, const int* in_sizes, int n_in,
                              void* d_out, int out_size) {
    const float* x    = (const float*)d_in[0];
    const int*   ei   = (const int*)d_in[1];
    const float* Wl0  = (const float*)d_in[2];
    const float* bl0  = (const float*)d_in[3];
    const float* Wr0  = (const float*)d_in[4];
    const float* Wl1  = (const float*)d_in[5];
    const float* bl1  = (const float*)d_in[6];
    const float* Wr1  = (const float*)d_in[7];
    const float* Wl2  = (const float*)d_in[8];
    const float* bl2  = (const float*)d_in[9];
    const float* Wr2  = (const float*)d_in[10];
    const float* Wp   = (const float*)d_in[11];
    const float* bp   = (const float*)d_in[12];
    const float* gamma = (const float*)d_in[13];
    const float* beta  = (const float*)d_in[14];

    float* out = (float*)d_out;
    float* x3 = out;                          // [N, 256]
    float* h  = out + (size_t)NN * DH;        // [N, 128]

    float *h1, *h2, *z;
    unsigned *aggh, *aggl, *h1h, *h1l, *h2h, *h2l, *x3h, *x3l, *xh, *xl;
    unsigned *wl0h, *wl0l, *wr0h, *wr0l, *wl1h, *wl1l, *wr1h, *wr1l;
    unsigned *wl2h, *wl2l, *wr2h, *wr2l, *wph, *wpl;
    cudaGetSymbolAddress((void**)&h1, g_h1);
    cudaGetSymbolAddress((void**)&h2, g_h2);
    cudaGetSymbolAddress((void**)&z, g_z);
    cudaGetSymbolAddress((void**)&aggh, g_aggh);
    cudaGetSymbolAddress((void**)&aggl, g_aggl);
    cudaGetSymbolAddress((void**)&h1h, g_h1h);
    cudaGetSymbolAddress((void**)&h1l, g_h1l);
    cudaGetSymbolAddress((void**)&h2h, g_h2h);
    cudaGetSymbolAddress((void**)&h2l, g_h2l);
    cudaGetSymbolAddress((void**)&x3h, g_x3h);
    cudaGetSymbolAddress((void**)&x3l, g_x3l);
    cudaGetSymbolAddress((void**)&xh, g_xh);
    cudaGetSymbolAddress((void**)&xl, g_xl);
    cudaGetSymbolAddress((void**)&wl0h, g_wl0h);
    cudaGetSymbolAddress((void**)&wl0l, g_wl0l);
    cudaGetSymbolAddress((void**)&wr0h, g_wr0h);
    cudaGetSymbolAddress((void**)&wr0l, g_wr0l);
    cudaGetSymbolAddress((void**)&wl1h, g_wl1h);
    cudaGetSymbolAddress((void**)&wl1l, g_wl1l);
    cudaGetSymbolAddress((void**)&wr1h, g_wr1h);
    cudaGetSymbolAddress((void**)&wr1l, g_wr1l);
    cudaGetSymbolAddress((void**)&wl2h, g_wl2h);
    cudaGetSymbolAddress((void**)&wl2l, g_wl2l);
    cudaGetSymbolAddress((void**)&wr2h, g_wr2h);
    cudaGetSymbolAddress((void**)&wr2l, g_wr2l);
    cudaGetSymbolAddress((void**)&wph, g_wph);
    cudaGetSymbolAddress((void**)&wpl, g_wpl);

    // CSR build
    zero_kernel<<<(NN + 255) / 256, 256>>>();
    count_deg_kernel<<<2048, 256>>>(ei);
    scan1_kernel<<<NBLK, SCAN_B>>>();
    scan2_kernel<<<1, 32>>>();
    scan3_kernel<<<(NN + 255) / 256, 256>>>();
    fill_csr_kernel<<<2048, 256>>>(ei);

    // pre-split weights + x
    split_f_kernel<<<64, 256>>>(Wl0, wl0h, wl0l, DH, DIN, KW0);
    split_f_kernel<<<64, 256>>>(Wr0, wr0h, wr0l, DH, DIN, KW0);
    split_f_kernel<<<64, 256>>>(Wl1, wl1h, wl1l, DH, DH, KW1);
    split_f_kernel<<<64, 256>>>(Wr1, wr1h, wr1l, DH, DH, KW1);
    split_f_kernel<<<64, 256>>>(Wl2, wl2h, wl2l, DH, DH, KW1);
    split_f_kernel<<<64, 256>>>(Wr2, wr2h, wr2l, DH, DH, KW1);
    split_f_kernel<<<64, 256>>>(Wp, wph, wpl, DPP, DH, KW1);
    split_f_kernel<<<2048, 256>>>(x, xh, xl, NN, DIN, KW0);

    int aggBlocks = (NN + 7) / 8;   // 8 warps per block, 1 warp/node
    dim3 grid256(DH / 128, (NN + 127) / 128);
    dim3 grid128(DPP / 128, (NN + 127) / 128);

    // layer 0
    agg100s_kernel<<<aggBlocks, 256>>>(x, aggh, aggl);
    mma_gemm2_kernel<true, true, true><<<grid256, 256>>>(
        aggh, aggl, xh, xl, wl0h, wl0l, wr0h, wr0l, bl0,
        h1, h1h, h1l, NN, DH, KW0, KW0);
    // layer 1
    agg256s_kernel<<<aggBlocks, 256>>>(h1, aggh, aggl);
    mma_gemm2_kernel<true, true, true><<<grid256, 256>>>(
        aggh, aggl, h1h, h1l, wl1h, wl1l, wr1h, wr1l, bl1,
        h2, h2h, h2l, NN, DH, KW1, KW1);
    // layer 2 (no relu), writes x3 into d_out + split for projection
    agg256s_kernel<<<aggBlocks, 256>>>(h2, aggh, aggl);
    mma_gemm2_kernel<true, false, true><<<grid256, 256>>>(
        aggh, aggl, h2h, h2l, wl2h, wl2l, wr2h, wr2l, bl2,
        x3, x3h, x3l, NN, DH, KW1, KW1);
    // projection
    mma_gemm2_kernel<false, false, false><<<grid128, 256>>>(
        x3h, x3l, (const unsigned*)0, (const unsigned*)0,
        wph, wpl, (const unsigned*)0, (const unsigned*)0, bp,
        z, (unsigned*)0, (unsigned*)0, NN, DPP, KW1, KW1);
    // BatchNorm
    bn_reduce_kernel<<<512, DPP>>>();
    bn_fin_kernel<<<1, DPP>>>();
    bn_apply_kernel<<<2048, 256>>>(gamma, beta, h);
}

// round 5
// speedup vs baseline: 1.9669x; 1.0702x over previous
#include <cuda_runtime.h>
#include <cuda_bf16.h>
#include <math.h>

#define NN 100000
#define EE 1600000
#define DIN 100
#define KW0 56          // u32 width for K=100 padded to 112 bf16
#define DH  256
#define KW1 128         // u32 width for K=256
#define DPP 128
#define SCAN_B 1024
#define NBLK ((NN + SCAN_B - 1) / SCAN_B)   // 98

// ---------------- scratch (device globals; no allocation allowed) ----------
__device__ __align__(16) float    g_h1 [(size_t)NN * DH];
__device__ __align__(16) float    g_h2 [(size_t)NN * DH];
__device__ __align__(16) float    g_z  [(size_t)NN * DPP];
__device__ __align__(16) unsigned g_aggh[(size_t)NN * KW1];
__device__ __align__(16) unsigned g_aggl[(size_t)NN * KW1];
__device__ __align__(16) unsigned g_h1h[(size_t)NN * KW1];
__device__ __align__(16) unsigned g_h1l[(size_t)NN * KW1];
__device__ __align__(16) unsigned g_h2h[(size_t)NN * KW1];
__device__ __align__(16) unsigned g_h2l[(size_t)NN * KW1];
__device__ __align__(16) unsigned g_x3h[(size_t)NN * KW1];
__device__ __align__(16) unsigned g_x3l[(size_t)NN * KW1];
__device__ __align__(16) unsigned g_xh [(size_t)NN * KW0];
__device__ __align__(16) unsigned g_xl [(size_t)NN * KW0];
// weights split
__device__ __align__(16) unsigned g_wl0h[DH * KW0], g_wl0l[DH * KW0];
__device__ __align__(16) unsigned g_wr0h[DH * KW0], g_wr0l[DH * KW0];
__device__ __align__(16) unsigned g_wl1h[DH * KW1], g_wl1l[DH * KW1];
__device__ __align__(16) unsigned g_wr1h[DH * KW1], g_wr1l[DH * KW1];
__device__ __align__(16) unsigned g_wl2h[DH * KW1], g_wl2l[DH * KW1];
__device__ __align__(16) unsigned g_wr2h[DH * KW1], g_wr2l[DH * KW1];
__device__ __align__(16) unsigned g_wph [DPP * KW1], g_wpl[DPP * KW1];

__device__ int   g_deg[NN];
__device__ int   g_off[NN];
__device__ int   g_pos[NN];
__device__ float g_rdeg[NN];
__device__ int   g_csr[EE];
__device__ int   g_bsum[NBLK];
__device__ float g_sum[DPP], g_sumsq[DPP], g_mu[DPP], g_rsig[DPP];

// ---------------- helpers ----------------------------------------------------
__device__ __forceinline__ void split2(float v0, float v1,
                                       unsigned& hi, unsigned& lo) {
    float h0 = __bfloat162float(__float2bfloat16(v0));
    float h1 = __bfloat162float(__float2bfloat16(v1));
    float l0 = v0 - h0;
    float l1 = v1 - h1;
    asm("cvt.rn.bf16x2.f32 %0, %1, %2;" : "=r"(hi) : "f"(h1), "f"(h0));
    asm("cvt.rn.bf16x2.f32 %0, %1, %2;" : "=r"(lo) : "f"(l1), "f"(l0));
}

__device__ __forceinline__ void mma16816(float c[4], const unsigned a[4],
                                         const unsigned b[2]) {
    asm volatile(
        "mma.sync.aligned.m16n8k16.row.col.f32.bf16.bf16.f32 "
        "{%0,%1,%2,%3}, {%4,%5,%6,%7}, {%8,%9}, {%0,%1,%2,%3};"
        : "+f"(c[0]), "+f"(c[1]), "+f"(c[2]), "+f"(c[3])
        : "r"(a[0]), "r"(a[1]), "r"(a[2]), "r"(a[3]), "r"(b[0]), "r"(b[1]));
}

__device__ __forceinline__ void ldsm_x4(unsigned r[4], unsigned addr) {
    asm volatile(
        "ldmatrix.sync.aligned.m8n8.x4.shared.b16 {%0,%1,%2,%3}, [%4];"
        : "=r"(r[0]), "=r"(r[1]), "=r"(r[2]), "=r"(r[3]) : "r"(addr));
}

__device__ __forceinline__ void cp16(unsigned dst, const void* src) {
    asm volatile("cp.async.cg.shared.global [%0], [%1], 16;"
                 :: "r"(dst), "l"(src) : "memory");
}
__device__ __forceinline__ void cp_commit() {
    asm volatile("cp.async.commit_group;" ::: "memory");
}
__device__ __forceinline__ void cp_wait1() {
    asm volatile("cp.async.wait_group 1;" ::: "memory");
}

// ---------------- CSR build -------------------------------------------------
__global__ void zero_kernel() {
    int i = blockIdx.x * blockDim.x + threadIdx.x;
    if (i < NN) g_deg[i] = 0;
    if (i < DPP) { g_sum[i] = 0.f; g_sumsq[i] = 0.f; }
}

__global__ void count_deg_kernel(const int* __restrict__ ei) {
    for (int e = blockIdx.x * blockDim.x + threadIdx.x; e < EE;
         e += gridDim.x * blockDim.x) {
        atomicAdd(&g_deg[ei[EE + e]], 1);
    }
}

__global__ void scan1_kernel() {
    __shared__ int sh[SCAN_B];
    int tid = threadIdx.x;
    int i = blockIdx.x * SCAN_B + tid;
    int v = (i < NN) ? g_deg[i] : 0;
    sh[tid] = v;
    __syncthreads();
    for (int off = 1; off < SCAN_B; off <<= 1) {
        int t = (tid >= off) ? sh[tid - off] : 0;
        __syncthreads();
        sh[tid] += t;
        __syncthreads();
    }
    if (i < NN) g_off[i] = sh[tid] - v;   // exclusive
    if (tid == SCAN_B - 1) g_bsum[blockIdx.x] = sh[tid];
}

__global__ void scan2_kernel() {
    if (threadIdx.x == 0 && blockIdx.x == 0) {
        int acc = 0;
        for (int b = 0; b < NBLK; b++) { int t = g_bsum[b]; g_bsum[b] = acc; acc += t; }
    }
}

__global__ void scan3_kernel() {
    int i = blockIdx.x * blockDim.x + threadIdx.x;
    if (i < NN) {
        int o = g_off[i] + g_bsum[i / SCAN_B];
        g_off[i] = o;
        g_pos[i] = o;
        int d = g_deg[i];
        g_rdeg[i] = 1.f / (float)(d > 1 ? d : 1);
    }
}

__global__ void fill_csr_kernel(const int* __restrict__ ei) {
    for (int e = blockIdx.x * blockDim.x + threadIdx.x; e < EE;
         e += gridDim.x * blockDim.x) {
        int dst = ei[EE + e];
        int p = atomicAdd(&g_pos[dst], 1);
        g_csr[p] = ei[e];
    }
}

// ---------------- generic fp32 -> packed bf16 hi/lo split -------------------
__global__ void split_f_kernel(const float* __restrict__ src,
                               unsigned* __restrict__ hi, unsigned* __restrict__ lo,
                               int rows, int K, int Kw) {
    size_t total = (size_t)rows * Kw;
    for (size_t idx = (size_t)blockIdx.x * blockDim.x + threadIdx.x; idx < total;
         idx += (size_t)gridDim.x * blockDim.x) {
        int r = (int)(idx / Kw);
        int c = (int)(idx % Kw);
        int k = 2 * c;
        const float* p = src + (size_t)r * K;
        float v0 = (k < K) ? p[k] : 0.f;
        float v1 = (k + 1 < K) ? p[k + 1] : 0.f;
        unsigned h, l;
        split2(v0, v1, h, l);
        hi[idx] = h;
        lo[idx] = l;
    }
}

// ---------------- aggregation (mean), emits packed hi/lo --------------------
__global__ void agg256s_kernel(const float* __restrict__ xin,
                               unsigned* __restrict__ oh, unsigned* __restrict__ ol) {
    int gw = (blockIdx.x * blockDim.x + threadIdx.x) >> 5;
    int lane = threadIdx.x & 31;
    if (gw >= NN) return;
    int beg = g_off[gw];
    int cnt = g_deg[gw];
    float4 a0 = make_float4(0.f, 0.f, 0.f, 0.f);
    float4 a1 = make_float4(0.f, 0.f, 0.f, 0.f);
    int j = 0;
    for (; j + 2 <= cnt; j += 2) {
        int s1 = g_csr[beg + j];
        int s2 = g_csr[beg + j + 1];
        const float4* r1 = (const float4*)(xin + (size_t)s1 * DH);
        const float4* r2 = (const float4*)(xin + (size_t)s2 * DH);
        float4 v0 = r1[lane], v1 = r1[lane + 32];
        float4 u0 = r2[lane], u1 = r2[lane + 32];
        a0.x += v0.x + u0.x; a0.y += v0.y + u0.y; a0.z += v0.z + u0.z; a0.w += v0.w + u0.w;
        a1.x += v1.x + u1.x; a1.y += v1.y + u1.y; a1.z += v1.z + u1.z; a1.w += v1.w + u1.w;
    }
    if (j < cnt) {
        int s1 = g_csr[beg + j];
        const float4* r1 = (const float4*)(xin + (size_t)s1 * DH);
        float4 v0 = r1[lane], v1 = r1[lane + 32];
        a0.x += v0.x; a0.y += v0.y; a0.z += v0.z; a0.w += v0.w;
        a1.x += v1.x; a1.y += v1.y; a1.z += v1.z; a1.w += v1.w;
    }
    float rd = g_rdeg[gw];
    a0.x *= rd; a0.y *= rd; a0.z *= rd; a0.w *= rd;
    a1.x *= rd; a1.y *= rd; a1.z *= rd; a1.w *= rd;
    unsigned h0, l0, h1, l1;
    size_t base = (size_t)gw * KW1;
    split2(a0.x, a0.y, h0, l0);
    split2(a0.z, a0.w, h1, l1);
    oh[base + lane * 2] = h0; oh[base + lane * 2 + 1] = h1;
    ol[base + lane * 2] = l0; ol[base + lane * 2 + 1] = l1;
    split2(a1.x, a1.y, h0, l0);
    split2(a1.z, a1.w, h1, l1);
    oh[base + 64 + lane * 2] = h0; oh[base + 64 + lane * 2 + 1] = h1;
    ol[base + 64 + lane * 2] = l0; ol[base + 64 + lane * 2 + 1] = l1;
}

__global__ void agg100s_kernel(const float* __restrict__ xin,
                               unsigned* __restrict__ oh, unsigned* __restrict__ ol) {
    int gw = (blockIdx.x * blockDim.x + threadIdx.x) >> 5;
    int lane = threadIdx.x & 31;
    if (gw >= NN) return;
    int beg = g_off[gw];
    int cnt = g_deg[gw];
    float4 a = make_float4(0.f, 0.f, 0.f, 0.f);
    bool act = lane < 25;   // 25 float4 = 100 floats
    int j = 0;
    for (; j + 2 <= cnt; j += 2) {
        int s1 = g_csr[beg + j];
        int s2 = g_csr[beg + j + 1];
        if (act) {
            const float4* r1 = (const float4*)(xin + (size_t)s1 * DIN);
            const float4* r2 = (const float4*)(xin + (size_t)s2 * DIN);
            float4 v = r1[lane];
            float4 u = r2[lane];
            a.x += v.x + u.x; a.y += v.y + u.y; a.z += v.z + u.z; a.w += v.w + u.w;
        }
    }
    if (j < cnt) {
        int s1 = g_csr[beg + j];
        if (act) {
            const float4* r1 = (const float4*)(xin + (size_t)s1 * DIN);
            float4 v = r1[lane];
            a.x += v.x; a.y += v.y; a.z += v.z; a.w += v.w;
        }
    }
    float rd = g_rdeg[gw];
    a.x *= rd; a.y *= rd; a.z *= rd; a.w *= rd;
    if (!act) { a.x = a.y = a.z = a.w = 0.f; }
    if (lane < 28) {
        unsigned h0, l0, h1, l1;
        split2(a.x, a.y, h0, l0);
        split2(a.z, a.w, h1, l1);
        size_t base = (size_t)gw * KW0;
        oh[base + lane * 2] = h0; oh[base + lane * 2 + 1] = h1;
        ol[base + lane * 2] = l0; ol[base + lane * 2 + 1] = l1;
    }
}

// ---------------- tensor-core GEMM: 256x128 CTA, warp 64x64, cp.async x3 ----
// smem per stage: Ah[256x12u] Al Wh[128x12u] Wl  (48B row stride, LDSM-friendly)
#define BM 256
#define BN 128
#define SRU 12                       // u32 row stride
#define OFF_AL 12288                 // bytes
#define OFF_WH 24576
#define OFF_WL 30720
#define STAGE_B 36864                // bytes per stage
#define NSTG 3
#define SMEM_DYN (STAGE_B * NSTG)    // 110592 B

template <bool DUAL, bool RELU, bool SPLIT_OUT>
__global__ void __launch_bounds__(256, 1)
mma_gemm3_kernel(const unsigned* __restrict__ Ah, const unsigned* __restrict__ Al,
                 const unsigned* __restrict__ Xh, const unsigned* __restrict__ Xl,
                 const unsigned* __restrict__ WlH, const unsigned* __restrict__ WlL,
                 const unsigned* __restrict__ WrH, const unsigned* __restrict__ WrL,
                 const float* __restrict__ bias, float* __restrict__ Y,
                 unsigned* __restrict__ Yh, unsigned* __restrict__ Yl,
                 int M, int Nn, int KwA, int KwX) {
    extern __shared__ unsigned dynsm[];
    const unsigned sbase = (unsigned)__cvta_generic_to_shared(dynsm);

    const int tid = threadIdx.x;
    const int lane = tid & 31;
    const int wid = tid >> 5;
    const int wm = wid & 3;        // 4 warp rows x 64
    const int wn = wid >> 2;       // 2 warp cols x 64
    const int g = lane >> 2;
    const int tq = lane & 3;

    const int m0 = blockIdx.y * BM;
    const int n0 = blockIdx.x * BN;

    const int sA = KwA >> 3;
    const int nsteps = DUAL ? sA + (KwX >> 3) : sA;

    // LDSM per-lane offsets (u32 units within a tile)
    const unsigned laneA = ((lane & 7) + ((lane >> 3) & 1) * 8) * SRU +
                           ((lane >> 4) & 1) * 4;
    const unsigned laneB = ((lane & 7) + ((lane >> 4) & 1) * 8) * SRU +
                           ((lane >> 3) & 1) * 4;

    float acc[4][8][4];
#pragma unroll
    for (int i = 0; i < 4; i++)
#pragma unroll
        for (int j = 0; j < 8; j++)
#pragma unroll
            for (int e = 0; e < 4; e++) acc[i][j][e] = 0.f;

    // loader indices
    const int arow = tid;                 // 0..255
    const int brow = tid >> 1;            // 0..127
    const int bch = tid & 1;

    auto issue = [&](int st, int buf) {
        const unsigned *Mh, *Ml, *Wh, *Wl;
        int Kw, kw0;
        if (!DUAL || st < sA) { Mh = Ah; Ml = Al; Wh = WlH; Wl = WlL; Kw = KwA; kw0 = st * 8; }
        else                  { Mh = Xh; Ml = Xl; Wh = WrH; Wl = WrL; Kw = KwX; kw0 = (st - sA) * 8; }
        unsigned sb = sbase + buf * STAGE_B;
        int gm = m0 + arow; if (gm >= M) gm = M - 1;   // clamp: garbage rows discarded in epilogue
        size_t offm = (size_t)gm * Kw + kw0;
        cp16(sb + arow * 48,                Mh + offm);
        cp16(sb + arow * 48 + 16,           Mh + offm + 4);
        cp16(sb + OFF_AL + arow * 48,       Ml + offm);
        cp16(sb + OFF_AL + arow * 48 + 16,  Ml + offm + 4);
        int gn = n0 + brow;                             // Nn is multiple of 128
        size_t offn = (size_t)gn * Kw + kw0 + bch * 4;
        cp16(sb + OFF_WH + brow * 48 + bch * 16, Wh + offn);
        cp16(sb + OFF_WL + brow * 48 + bch * 16, Wl + offn);
    };

    auto compute = [&](int buf) {
        unsigned sb = sbase + buf * STAGE_B;
        unsigned aHb = sb + (unsigned)(wm * 64 * SRU + laneA) * 4;
        unsigned aLb = aHb + OFF_AL;
        unsigned wHb = sb + OFF_WH + (unsigned)(wn * 64 * SRU + laneB) * 4;
        unsigned wLb = wHb + (OFF_WL - OFF_WH);
        unsigned bh[8][2], bl[8][2];
#pragma unroll
        for (int p = 0; p < 4; p++) {
            unsigned r[4];
            ldsm_x4(r, wHb + p * 16 * 48);
            bh[2 * p][0] = r[0]; bh[2 * p][1] = r[1];
            bh[2 * p + 1][0] = r[2]; bh[2 * p + 1][1] = r[3];
            ldsm_x4(r, wLb + p * 16 * 48);
            bl[2 * p][0] = r[0]; bl[2 * p][1] = r[1];
            bl[2 * p + 1][0] = r[2]; bl[2 * p + 1][1] = r[3];
        }
#pragma unroll
        for (int mr = 0; mr < 4; mr++) {
            unsigned ah[4], al[4];
            ldsm_x4(ah, aHb + mr * 16 * 48);
            ldsm_x4(al, aLb + mr * 16 * 48);
#pragma unroll
            for (int nb = 0; nb < 8; nb++) {
                mma16816(acc[mr][nb], ah, bh[nb]);
                mma16816(acc[mr][nb], ah, bl[nb]);
                mma16816(acc[mr][nb], al, bh[nb]);
            }
        }
    };

    // ---- 3-stage pipeline, single sync per k-step ----
    issue(0, 0); cp_commit();
    if (nsteps > 1) { issue(1, 1); cp_commit(); }
    for (int s = 0; s < nsteps; s++) {
        cp_wait1();
        __syncthreads();
        if (s + NSTG - 1 < nsteps) issue(s + NSTG - 1, (s + NSTG - 1) % NSTG);
        cp_commit();               // always commit (possibly empty) to keep wait semantics
        compute(s % NSTG);
    }

    // ---- epilogue ----
    const int Nw = Nn >> 1;
#pragma unroll
    for (int mr = 0; mr < 4; mr++) {
#pragma unroll
        for (int nb = 0; nb < 8; nb++) {
            int n = n0 + wn * 64 + nb * 8 + tq * 2;
            float b0 = bias[n];
            float b1 = bias[n + 1];
            int mA = m0 + wm * 64 + mr * 16 + g;
            int mB = mA + 8;
            float v0 = acc[mr][nb][0] + b0;
            float v1 = acc[mr][nb][1] + b1;
            float v2 = acc[mr][nb][2] + b0;
            float v3 = acc[mr][nb][3] + b1;
            if (RELU) {
                v0 = fmaxf(v0, 0.f); v1 = fmaxf(v1, 0.f);
                v2 = fmaxf(v2, 0.f); v3 = fmaxf(v3, 0.f);
            }
            if (mA < M) {
                *(float2*)(Y + (size_t)mA * Nn + n) = make_float2(v0, v1);
                if (SPLIT_OUT) {
                    unsigned hh, ll;
                    split2(v0, v1, hh, ll);
                    Yh[(size_t)mA * Nw + (n >> 1)] = hh;
                    Yl[(size_t)mA * Nw + (n >> 1)] = ll;
                }
            }
            if (mB < M) {
                *(float2*)(Y + (size_t)mB * Nn + n) = make_float2(v2, v3);
                if (SPLIT_OUT) {
                    unsigned hh, ll;
                    split2(v2, v3, hh, ll);
                    Yh[(size_t)mB * Nw + (n >> 1)] = hh;
                    Yl[(size_t)mB * Nw + (n >> 1)] = ll;
                }
            }
        }
    }
}

// ---------------- BatchNorm --------------------------------------------------
__global__ void bn_reduce_kernel() {
    int c = threadIdx.x;
    float s = 0.f, s2 = 0.f;
    for (int m = blockIdx.x; m < NN; m += gridDim.x) {
        float v = g_z[(size_t)m * DPP + c];
        s += v;
        s2 += v * v;
    }
    atomicAdd(&g_sum[c], s);
    atomicAdd(&g_sumsq[c], s2);
}

__global__ void bn_fin_kernel() {
    int c = threadIdx.x;
    if (c < DPP) {
        float mu = g_sum[c] / (float)NN;
        float var = g_sumsq[c] / (float)NN - mu * mu;
        g_mu[c] = mu;
        g_rsig[c] = rsqrtf(var + 1e-5f);
    }
}

__global__ void bn_apply_kernel(const float* __restrict__ gamma,
                                const float* __restrict__ beta,
                                float* __restrict__ h) {
    for (size_t idx = (size_t)blockIdx.x * blockDim.x + threadIdx.x;
         idx < (size_t)NN * DPP; idx += (size_t)gridDim.x * blockDim.x) {
        int c = (int)(idx & (DPP - 1));
        float v = g_z[idx];
        h[idx] = gamma[c] * (v - g_mu[c]) * g_rsig[c] + beta[c];
    }
}

// ---------------- launch -----------------------------------------------------
extern "C" void kernel_launch(void* const* d_in, const int* in_sizes, int n_in,
                              void* d_out, int out_size) {
    const float* x    = (const float*)d_in[0];
    const int*   ei   = (const int*)d_in[1];
    const float* Wl0  = (const float*)d_in[2];
    const float* bl0  = (const float*)d_in[3];
    const float* Wr0  = (const float*)d_in[4];
    const float* Wl1  = (const float*)d_in[5];
    const float* bl1  = (const float*)d_in[6];
    const float* Wr1  = (const float*)d_in[7];
    const float* Wl2  = (const float*)d_in[8];
    const float* bl2  = (const float*)d_in[9];
    const float* Wr2  = (const float*)d_in[10];
    const float* Wp   = (const float*)d_in[11];
    const float* bp   = (const float*)d_in[12];
    const float* gamma = (const float*)d_in[13];
    const float* beta  = (const float*)d_in[14];

    float* out = (float*)d_out;
    float* x3 = out;                          // [N, 256]
    float* h  = out + (size_t)NN * DH;        // [N, 128]

    float *h1, *h2, *z;
    unsigned *aggh, *aggl, *h1h, *h1l, *h2h, *h2l, *x3h, *x3l, *xh, *xl;
    unsigned *wl0h, *wl0l, *wr0h, *wr0l, *wl1h, *wl1l, *wr1h, *wr1l;
    unsigned *wl2h, *wl2l, *wr2h, *wr2l, *wph, *wpl;
    cudaGetSymbolAddress((void**)&h1, g_h1);
    cudaGetSymbolAddress((void**)&h2, g_h2);
    cudaGetSymbolAddress((void**)&z, g_z);
    cudaGetSymbolAddress((void**)&aggh, g_aggh);
    cudaGetSymbolAddress((void**)&aggl, g_aggl);
    cudaGetSymbolAddress((void**)&h1h, g_h1h);
    cudaGetSymbolAddress((void**)&h1l, g_h1l);
    cudaGetSymbolAddress((void**)&h2h, g_h2h);
    cudaGetSymbolAddress((void**)&h2l, g_h2l);
    cudaGetSymbolAddress((void**)&x3h, g_x3h);
    cudaGetSymbolAddress((void**)&x3l, g_x3l);
    cudaGetSymbolAddress((void**)&xh, g_xh);
    cudaGetSymbolAddress((void**)&xl, g_xl);
    cudaGetSymbolAddress((void**)&wl0h, g_wl0h);
    cudaGetSymbolAddress((void**)&wl0l, g_wl0l);
    cudaGetSymbolAddress((void**)&wr0h, g_wr0h);
    cudaGetSymbolAddress((void**)&wr0l, g_wr0l);
    cudaGetSymbolAddress((void**)&wl1h, g_wl1h);
    cudaGetSymbolAddress((void**)&wl1l, g_wl1l);
    cudaGetSymbolAddress((void**)&wr1h, g_wr1h);
    cudaGetSymbolAddress((void**)&wr1l, g_wr1l);
    cudaGetSymbolAddress((void**)&wl2h, g_wl2h);
    cudaGetSymbolAddress((void**)&wl2l, g_wl2l);
    cudaGetSymbolAddress((void**)&wr2h, g_wr2h);
    cudaGetSymbolAddress((void**)&wr2l, g_wr2l);
    cudaGetSymbolAddress((void**)&wph, g_wph);
    cudaGetSymbolAddress((void**)&wpl, g_wpl);

    // raise dyn-smem limits (host-side attribute set; not graph work)
    cudaFuncSetAttribute(mma_gemm3_kernel<true, true, true>,
                         cudaFuncAttributeMaxDynamicSharedMemorySize, SMEM_DYN);
    cudaFuncSetAttribute(mma_gemm3_kernel<true, false, true>,
                         cudaFuncAttributeMaxDynamicSharedMemorySize, SMEM_DYN);
    cudaFuncSetAttribute(mma_gemm3_kernel<false, false, false>,
                         cudaFuncAttributeMaxDynamicSharedMemorySize, SMEM_DYN);

    // CSR build
    zero_kernel<<<(NN + 255) / 256, 256>>>();
    count_deg_kernel<<<2048, 256>>>(ei);
    scan1_kernel<<<NBLK, SCAN_B>>>();
    scan2_kernel<<<1, 32>>>();
    scan3_kernel<<<(NN + 255) / 256, 256>>>();
    fill_csr_kernel<<<2048, 256>>>(ei);

    // pre-split weights + x
    split_f_kernel<<<64, 256>>>(Wl0, wl0h, wl0l, DH, DIN, KW0);
    split_f_kernel<<<64, 256>>>(Wr0, wr0h, wr0l, DH, DIN, KW0);
    split_f_kernel<<<64, 256>>>(Wl1, wl1h, wl1l, DH, DH, KW1);
    split_f_kernel<<<64, 256>>>(Wr1, wr1h, wr1l, DH, DH, KW1);
    split_f_kernel<<<64, 256>>>(Wl2, wl2h, wl2l, DH, DH, KW1);
    split_f_kernel<<<64, 256>>>(Wr2, wr2h, wr2l, DH, DH, KW1);
    split_f_kernel<<<64, 256>>>(Wp, wph, wpl, DPP, DH, KW1);
    split_f_kernel<<<2048, 256>>>(x, xh, xl, NN, DIN, KW0);

    int aggBlocks = (NN + 7) / 8;   // 8 warps per block, 1 warp/node
    dim3 grid256(DH / BN, (NN + BM - 1) / BM);
    dim3 grid128(DPP / BN, (NN + BM - 1) / BM);

    // layer 0
    agg100s_kernel<<<aggBlocks, 256>>>(x, aggh, aggl);
    mma_gemm3_kernel<true, true, true><<<grid256, 256, SMEM_DYN>>>(
        aggh, aggl, xh, xl, wl0h, wl0l, wr0h, wr0l, bl0,
        h1, h1h, h1l, NN, DH, KW0, KW0);
    // layer 1
    agg256s_kernel<<<aggBlocks, 256>>>(h1, aggh, aggl);
    mma_gemm3_kernel<true, true, true><<<grid256, 256, SMEM_DYN>>>(
        aggh, aggl, h1h, h1l, wl1h, wl1l, wr1h, wr1l, bl1,
        h2, h2h, h2l, NN, DH, KW1, KW1);
    // layer 2 (no relu), writes x3 into d_out + split for projection
    agg256s_kernel<<<aggBlocks, 256>>>(h2, aggh, aggl);
    mma_gemm3_kernel<true, false, true><<<grid256, 256, SMEM_DYN>>>(
        aggh, aggl, h2h, h2l, wl2h, wl2l, wr2h, wr2l, bl2,
        x3, x3h, x3l, NN, DH, KW1, KW1);
    // projection
    mma_gemm3_kernel<false, false, false><<<grid128, 256, SMEM_DYN>>>(
        x3h, x3l, (const unsigned*)0, (const unsigned*)0,
        wph, wpl, (const unsigned*)0, (const unsigned*)0, bp,
        z, (unsigned*)0, (unsigned*)0, NN, DPP, KW1, KW1);
    // BatchNorm
    bn_reduce_kernel<<<512, DPP>>>();
    bn_fin_kernel<<<1, DPP>>>();
    bn_apply_kernel<<<2048, 256>>>(gamma, beta, h);
}